// round 17
// baseline (speedup 1.0000x reference)
#include <cuda_runtime.h>
#include <cuda_fp16.h>
#include <math.h>
#include <stdint.h>

#define BB 16
#define NN 1024
#define FIN 128
#define HH 32
#define KC 64
#define K2C 16
#define EPSF 1e-15f

// ---------------- device scratch ----------------
__device__ float g_x1[BB*NN*HH];
__device__ __half g_x1h[BB*NN*HH];
__device__ __half g_sh[BB*NN*KC];         // tanh(s1) fp16 (MMA operand)
__device__ float g_qn[BB*NN];
__device__ float g_dflat[BB*NN];          // rowsum(adj), atomic
__device__ float g_vol[BB];               // atomic
__device__ float g_tda[BB];               // atomic
__device__ float g_tdd[BB];
__device__ __half g_T[(size_t)BB*NN*NN];  // cdist*adj (fp16, no /vol)
__device__ float g_Y[BB*NN*HH];           // T@x1h (atomic, no /vol)
__device__ float g_x2[BB*NN*HH];
__device__ float g_s2[BB*NN*K2C];
__device__ __half g_s2eh[BB*NN*32];       // [s2 | 1 | 0...] fp16
__device__ float g_qs2[BB*NN];
__device__ float g_P[BB*NN*32];
__device__ float g_ss[BB*KC*KC];          // atomic
__device__ float g_red[BB*16*64];         // atomic: c<16 oadj | 16..31 ss2 | 32..63 outx
__device__ float g_den2[BB];              // atomic
__device__ float g_o1b[BB];
__device__ float g_o2b[BB];

// ---------------- helpers ----------------
__device__ __forceinline__ float blockReduceSum(float v){
    __shared__ float sh[32];
    int tid = threadIdx.x;
    int nth = blockDim.x;
    int lane = tid & 31, wid = tid >> 5;
    __syncthreads();
    #pragma unroll
    for(int o=16;o;o>>=1) v += __shfl_down_sync(0xffffffffu, v, o);
    if(lane==0) sh[wid] = v;
    __syncthreads();
    float r = (tid < (nth>>5)) ? sh[tid] : 0.f;
    if(wid==0){
        #pragma unroll
        for(int o=16;o;o>>=1) r += __shfl_down_sync(0xffffffffu, r, o);
        if(lane==0) sh[0] = r;
    }
    __syncthreads();
    return sh[0];
}

__device__ __forceinline__ uint32_t smem_u32(const void* p){
    uint32_t a;
    asm("{ .reg .u64 t; cvta.to.shared.u64 t, %1; cvt.u32.u64 %0, t; }" : "=r"(a) : "l"(p));
    return a;
}
__device__ __forceinline__ void ldsm_x4(uint32_t&r0,uint32_t&r1,uint32_t&r2,uint32_t&r3,uint32_t a){
    asm volatile("ldmatrix.sync.aligned.m8n8.x4.shared.b16 {%0,%1,%2,%3}, [%4];"
        :"=r"(r0),"=r"(r1),"=r"(r2),"=r"(r3):"r"(a));
}
__device__ __forceinline__ void ldsm_x4_t(uint32_t&r0,uint32_t&r1,uint32_t&r2,uint32_t&r3,uint32_t a){
    asm volatile("ldmatrix.sync.aligned.m8n8.x4.trans.shared.b16 {%0,%1,%2,%3}, [%4];"
        :"=r"(r0),"=r"(r1),"=r"(r2),"=r"(r3):"r"(a));
}
__device__ __forceinline__ void mma16816(float* c, uint32_t a0,uint32_t a1,uint32_t a2,uint32_t a3,
                                         uint32_t b0,uint32_t b1){
    asm volatile("mma.sync.aligned.m16n8k16.row.col.f32.f16.f16.f32 "
        "{%0,%1,%2,%3}, {%4,%5,%6,%7}, {%8,%9}, {%0,%1,%2,%3};"
        : "+f"(c[0]),"+f"(c[1]),"+f"(c[2]),"+f"(c[3])
        : "r"(a0),"r"(a1),"r"(a2),"r"(a3),"r"(b0),"r"(b1));
}
__device__ __forceinline__ void cp_async16(uint32_t smem_addr, const void* gptr){
    asm volatile("cp.async.ca.shared.global [%0], [%1], 16;" :: "r"(smem_addr), "l"(gptr));
}
__device__ __forceinline__ void cp_commit(){ asm volatile("cp.async.commit_group;" ::: "memory"); }
template<int N> __device__ __forceinline__ void cp_wait(){ asm volatile("cp.async.wait_group %0;" :: "n"(N) : "memory"); }

// ---------------- kernels ----------------
__global__ void zero_kernel(){
    int t = blockIdx.x*256 + threadIdx.x;
    int stride = gridDim.x*256;
    for(int i=t;i<BB;i+=stride){ g_tda[i]=0.f; g_vol[i]=0.f; g_den2[i]=0.f; }
    for(int i=t;i<BB*NN;i+=stride) g_dflat[i]=0.f;
    for(int i=t;i<BB*KC*KC;i+=stride) g_ss[i]=0.f;
    for(int i=t;i<BB*16*64;i+=stride) g_red[i]=0.f;
    for(int i=t;i<BB*NN*HH;i+=stride) g_Y[i]=0.f;
}

// Fused: x1 = x@W1+b1 ; s = tanh(x1@Wp+bp) (fp16 out); qn; ss += s^T s (atomics)
__global__ __launch_bounds__(128) void lin1pool_kernel(
        const float* __restrict__ x, const float* __restrict__ W1, const float* __restrict__ b1,
        const float* __restrict__ Wp, const float* __restrict__ bp){
    __shared__ float Ws[FIN][36];
    __shared__ float xt[2][32][68];
    __shared__ float Wps[HH][68];
    __shared__ float bps[KC];
    __shared__ float x1s[64][33];
    __shared__ float sS[64][68];
    int tid = threadIdx.x;                 // 128
    int colg = tid & 7, rowg = tid >> 3;
    int rowbase = blockIdx.x*64;
    int b = rowbase >> 10;
    for(int i=tid;i<FIN*32;i+=128){ int k=i>>5,c=i&31; Ws[k][c]=W1[i]; }
    for(int i=tid;i<HH*KC;i+=128){ int k=i>>6,c=i&63; Wps[k][c]=Wp[i]; }
    if(tid<KC) bps[tid]=bp[tid];
    for(int i=tid;i<2048;i+=128){ int r=i>>5,k=i&31; xt[0][k][r]=x[(size_t)(rowbase+r)*FIN + k]; }
    float acc[4][4] = {};
    #pragma unroll
    for(int kc=0;kc<4;kc++){
        __syncthreads();
        if(kc<3){
            int nb=(kc+1)&1;
            for(int i=tid;i<2048;i+=128){ int r=i>>5,k=i&31; xt[nb][k][r]=x[(size_t)(rowbase+r)*FIN + (kc+1)*32 + k]; }
        }
        int cb=kc&1;
        #pragma unroll
        for(int k=0;k<32;k++){
            float4 a = *(const float4*)&xt[cb][k][rowg*4];
            float4 w = *(const float4*)&Ws[kc*32+k][colg*4];
            float av[4]={a.x,a.y,a.z,a.w}, wv[4]={w.x,w.y,w.z,w.w};
            #pragma unroll
            for(int i=0;i<4;i++)
                #pragma unroll
                for(int j=0;j<4;j++) acc[i][j] += av[i]*wv[j];
        }
    }
    float4 bb = *(const float4*)&b1[colg*4];
    float bv[4]={bb.x,bb.y,bb.z,bb.w};
    #pragma unroll
    for(int i=0;i<4;i++){
        int lr = rowg*4+i;
        float4 res = make_float4(acc[i][0]+bv[0],acc[i][1]+bv[1],acc[i][2]+bv[2],acc[i][3]+bv[3]);
        *(float4*)&g_x1[(rowbase+lr)*HH + colg*4] = res;
        __align__(8) __half2 hh[2];
        hh[0]=__floats2half2_rn(res.x,res.y); hh[1]=__floats2half2_rn(res.z,res.w);
        *(uint2*)&g_x1h[(rowbase+lr)*HH + colg*4] = *(uint2*)hh;
        x1s[lr][colg*4+0]=res.x; x1s[lr][colg*4+1]=res.y;
        x1s[lr][colg*4+2]=res.z; x1s[lr][colg*4+3]=res.w;
    }
    __syncthreads();
    // pool phase
    {
        int r = tid>>1, half = tid&1;
        int cb2 = half*32;
        float sv[32];
        #pragma unroll
        for(int c=0;c<32;c++) sv[c]=bps[cb2+c];
        #pragma unroll
        for(int k=0;k<32;k++){
            float xk = x1s[r][k];
            #pragma unroll
            for(int c4=0;c4<8;c4++){
                float4 w = *(const float4*)&Wps[k][cb2+c4*4];
                sv[c4*4+0] += xk*w.x; sv[c4*4+1] += xk*w.y;
                sv[c4*4+2] += xk*w.z; sv[c4*4+3] += xk*w.w;
            }
        }
        float q = 0.f;
        int grow = rowbase + r;
        #pragma unroll
        for(int c=0;c<32;c++){ float s=tanhf(sv[c]); sv[c]=s; q += s*s; }
        #pragma unroll
        for(int c4=0;c4<8;c4++){
            float4 res = make_float4(sv[c4*4],sv[c4*4+1],sv[c4*4+2],sv[c4*4+3]);
            __align__(8) __half2 hh[2];
            hh[0]=__floats2half2_rn(res.x,res.y); hh[1]=__floats2half2_rn(res.z,res.w);
            *(uint2*)&g_sh[grow*KC + cb2 + c4*4] = *(uint2*)hh;
            *(float4*)&sS[r][cb2 + c4*4] = res;
        }
        q += __shfl_xor_sync(0xffffffffu, q, 1);
        if(half==0) g_qn[grow] = q;
    }
    __syncthreads();
    // ss phase (fp32)
    {
        int kg = tid>>3, lg = tid&7;
        float accs[4][8] = {};
        #pragma unroll 4
        for(int r=0;r<64;r++){
            float4 a  = *(const float4*)&sS[r][kg*4];
            float4 c0 = *(const float4*)&sS[r][lg*4];
            float4 c1 = *(const float4*)&sS[r][lg*4+32];
            float av[4]={a.x,a.y,a.z,a.w};
            float cv[8]={c0.x,c0.y,c0.z,c0.w,c1.x,c1.y,c1.z,c1.w};
            #pragma unroll
            for(int i=0;i<4;i++)
                #pragma unroll
                for(int j=0;j<8;j++) accs[i][j] += av[i]*cv[j];
        }
        #pragma unroll
        for(int i=0;i<4;i++)
            #pragma unroll
            for(int j=0;j<8;j++){
                int col = (j<4) ? lg*4+j : lg*4+32+(j-4);
                atomicAdd(&g_ss[(b*KC + kg*4+i)*KC + col], accs[i][j]);
            }
    }
}

// ct_main: per-block 128x128 tile. fp16 MMA Gram -> cdist -> T(fp16)
// adj via cp.async ping-pong; T staged in smem for coalesced writes;
// Y = T@x1h folded in (warp==ch does MMA on Tst x Xcol, atomicAdd to g_Y).
// accumulates tda, dflat, vol. grid (8,8,BB), 256 thr.
__global__ __launch_bounds__(256,2) void ct_main_kernel(const float* __restrict__ adj){
    __shared__ __align__(16) char smbuf[36864];     // Srow|Scol during MMA; adj1+Tst | Xcol after
    __shared__ __align__(16) float adj0[16][132];   // 8448B
    __shared__ float qa[128], qb[128];
    int b = blockIdx.z;
    int rowbase = blockIdx.y*128, colbase = blockIdx.x*128;
    int tid = threadIdx.x, w = tid>>5, lane = tid&31;
    int wr = (w>>2)*64, wc = (w&3)*32;
    const __half* Sh = g_sh + b*NN*KC;
    uint32_t sr_base = smem_u32(smbuf);             // Srow: 128x72 half
    uint32_t sc_base = sr_base + 18432;             // Scol: 128x72 half
    uint32_t adj1_b  = sr_base;                     // alias: adj1 16x132 float (8448B)
    uint32_t tst_b   = sr_base + 8448;              // alias: Tst 16x136 half (4352B)
    uint32_t xc_base = sc_base;                     // alias: Xcol 128x40 half (10240B)
    uint32_t adj0_b  = smem_u32(&adj0[0][0]);
    // G0: S tiles
    for(int i=tid;i<1024;i+=256){
        int r=i>>3, q=i&7;
        cp_async16(sr_base + (r*72+q*8)*2, &Sh[(rowbase+r)*KC + q*8]);
        cp_async16(sc_base + (r*72+q*8)*2, &Sh[(colbase+r)*KC + q*8]);
    }
    cp_commit();
    const float* Ap = adj + (size_t)b*NN*NN;
    // G1: adj chunk 0 -> adj0 (overlaps MMA)
    #pragma unroll
    for(int j=0;j<2;j++){
        int idx = tid + 256*j;
        int r = idx>>5, q = idx&31;
        cp_async16(adj0_b + (r*132+q*4)*4, &Ap[(size_t)(rowbase+r)*NN + colbase + q*4]);
    }
    cp_commit();
    if(tid<128) qa[tid] = g_qn[b*NN+rowbase+tid];
    else qb[tid-128] = g_qn[b*NN+colbase+(tid-128)];
    cp_wait<1>();          // S tiles ready; chunk0 may still be in flight
    __syncthreads();
    // MMA phase: warp tile 64x32
    float cf[4][4][4] = {};
    int a_row = lane & 15, a_half = lane >> 4;
    int b_row = (lane&7) + ((lane>>4)&1)*8;
    int b_koff = ((lane>>3)&1)*8;
    #pragma unroll
    for(int kk=0;kk<4;kk++){
        uint32_t a[4][4];
        #pragma unroll
        for(int mt=0;mt<4;mt++)
            ldsm_x4(a[mt][0],a[mt][1],a[mt][2],a[mt][3],
                sr_base + ((wr + mt*16 + a_row)*72 + kk*16 + a_half*8)*2);
        #pragma unroll
        for(int ng=0;ng<2;ng++){
            uint32_t b0,b1,b2,b3;
            ldsm_x4(b0,b1,b2,b3,
                sc_base + ((wc + ng*16 + b_row)*72 + kk*16 + b_koff)*2);
            #pragma unroll
            for(int mt=0;mt<4;mt++){
                mma16816(cf[mt][ng*2],   a[mt][0],a[mt][1],a[mt][2],a[mt][3], b0,b1);
                mma16816(cf[mt][ng*2+1], a[mt][0],a[mt][1],a[mt][2],a[mt][3], b2,b3);
            }
        }
    }
    __syncthreads();   // all ldsm reads done: S regions reusable
    // G2: Xcol = x1h[colbase:+128, 0:32] into old Scol region
    for(int i=tid;i<512;i+=256){
        int r=i>>2, q=i&3;
        cp_async16(xc_base + (r*40+q*8)*2, &g_x1h[(b*NN+colbase+r)*HH + q*8]);
    }
    cp_commit();
    // epilogue: 8 chunks of 16 rows, ping-pong adj buffers, staged T writes, Y MMA
    float tda = 0.f, volp = 0.f;
    __half* Tp = g_T + (size_t)b*NN*NN;
    int r_in = lane>>2, c_in = (lane&3)*2;
    int rgrp_w = w>>2;
    float cy[4][4] = {};
    #pragma unroll
    for(int ch=0;ch<8;ch++){
        if(ch+1<8){
            uint32_t dst = ((ch+1)&1) ? adj1_b : adj0_b;
            #pragma unroll
            for(int j=0;j<2;j++){
                int idx = tid + 256*j;
                int r = idx>>5, q = idx&31;
                cp_async16(dst + (r*132+q*4)*4,
                           &Ap[(size_t)(rowbase+(ch+1)*16+r)*NN + colbase + q*4]);
            }
            cp_commit();
            cp_wait<1>();
        } else {
            cp_wait<0>();
        }
        __syncthreads();
        // process chunk ch (active: warps with w>>2 == ch>>2)
        if(rgrp_w == (ch>>2)){
            int mt = ch&3;
            uint32_t src = (ch&1) ? adj1_b : adj0_b;
            #pragma unroll
            for(int h=0;h<2;h++){
                int lr = r_in + h*8;
                int row = rowbase + ch*16 + lr;
                float qai = qa[ch*16 + lr];
                float rp = 0.f;
                #pragma unroll
                for(int nt=0;nt<4;nt++){
                    int lc = wc + nt*8 + c_in;
                    float2 aj;
                    asm volatile("ld.shared.v2.f32 {%0,%1}, [%2];"
                        : "=f"(aj.x), "=f"(aj.y) : "r"(src + (lr*132+lc)*4));
                    float g0 = cf[mt][nt][h*2+0];
                    float g1 = cf[mt][nt][h*2+1];
                    float d0 = qai + qb[lc]   - 2.0f*g0;
                    float d1 = qai + qb[lc+1] - 2.0f*g1;
                    float r0 = sqrtf(fmaxf(d0, 0.f))*aj.x;
                    float r1 = sqrtf(fmaxf(d1, 0.f))*aj.y;
                    tda += aj.x*g0 + aj.y*g1;
                    rp  += aj.x + aj.y;
                    __half2 hv = __floats2half2_rn(r0, r1);
                    asm volatile("st.shared.b32 [%0], %1;"
                        :: "r"(tst_b + (lr*136+lc)*2), "r"(*(uint32_t*)&hv));
                }
                volp += rp;
                rp += __shfl_down_sync(0xffffffffu, rp, 1, 4);
                rp += __shfl_down_sync(0xffffffffu, rp, 2, 4);
                if((lane&3)==0) atomicAdd(&g_dflat[b*NN + row], rp);
            }
        }
        __syncthreads();
        // coalesced copy Tst -> global (all 256 threads, 16B each)
        {
            int row16 = tid>>4, q = tid&15;
            uint4 v;
            asm volatile("ld.shared.v4.b32 {%0,%1,%2,%3}, [%4];"
                : "=r"(v.x),"=r"(v.y),"=r"(v.z),"=r"(v.w)
                : "r"(tst_b + (row16*136 + q*8)*2));
            *(uint4*)&Tp[(size_t)(rowbase + ch*16 + row16)*NN + colbase + q*8] = v;
        }
        // Y-MMA: warp ch computes Y[ch rows 16][32] += Tst @ Xcol, atomicAdd
        if(w == ch){
            #pragma unroll
            for(int kk=0;kk<8;kk++){
                uint32_t a0,a1,a2,a3;
                ldsm_x4(a0,a1,a2,a3, tst_b + ((lane&15)*136 + kk*16 + (lane>>4)*8)*2);
                #pragma unroll
                for(int g=0;g<2;g++){
                    uint32_t b0,b1,b2,b3;
                    ldsm_x4_t(b0,b1,b2,b3,
                        xc_base + ((kk*16 + (lane&7) + ((lane>>3)&1)*8)*40 + g*16 + ((lane>>3)>>1)*8)*2);
                    mma16816(cy[2*g],   a0,a1,a2,a3, b0,b1);
                    mma16816(cy[2*g+1], a0,a1,a2,a3, b2,b3);
                }
            }
            float* Yp = g_Y + (size_t)(b*NN + rowbase + ch*16)*HH;
            int r0y = lane>>2, c0y = (lane&3)*2;
            #pragma unroll
            for(int nt=0;nt<4;nt++){
                atomicAdd(&Yp[r0y*HH + nt*8 + c0y],       cy[nt][0]);
                atomicAdd(&Yp[r0y*HH + nt*8 + c0y+1],     cy[nt][1]);
                atomicAdd(&Yp[(r0y+8)*HH + nt*8 + c0y],   cy[nt][2]);
                atomicAdd(&Yp[(r0y+8)*HH + nt*8 + c0y+1], cy[nt][3]);
            }
        }
        __syncthreads();
    }
    volp = blockReduceSum(volp);
    if(tid==0) atomicAdd(&g_vol[b], volp);
    tda = blockReduceSum(tda);
    if(tid==0) atomicAdd(&g_tda[b], tda);
}

// O[b] = invvol * (T[b] @ Xh[b]) via mma.m16n8k16 + cp.async 3-stage pipeline
#define BST 3
__device__ __forceinline__ void bmm_mma(const __half* __restrict__ Xh, float* __restrict__ O){
    __shared__ __align__(16) __half At[BST][64][72];
    __shared__ __align__(16) __half Xs[BST][64][40];
    int b = blockIdx.y, rowbase = blockIdx.x*64;
    int tid = threadIdx.x;
    int w = tid>>5, lane = tid&31;
    int wr = (w&3)*16, wc = (w>>2)*16;
    const __half* Ab = g_T + (size_t)b*NN*NN;
    const __half* Xb = Xh + (size_t)b*NN*32;
    float c[2][4] = {};
    uint32_t at_base = smem_u32(&At[0][0][0]);
    uint32_t xs_base = smem_u32(&Xs[0][0][0]);
    int tr0 = tid>>3,        tq0 = tid&7;
    int tr1 = (tid+256)>>3,  tq1 = (tid+256)&7;
    int xr  = tid>>2,        xq  = tid&3;
    #pragma unroll
    for(int s=0;s<BST;s++){
        size_t ko = (size_t)s*64;
        cp_async16(at_base + (s*64*72 + tr0*72 + tq0*8)*2, &Ab[(size_t)(rowbase+tr0)*NN + ko + tq0*8]);
        cp_async16(at_base + (s*64*72 + tr1*72 + tq1*8)*2, &Ab[(size_t)(rowbase+tr1)*NN + ko + tq1*8]);
        cp_async16(xs_base + (s*64*40 + xr*40 + xq*8)*2,   &Xb[(ko+xr)*32 + xq*8]);
        cp_commit();
    }
    int a_row = lane & 15, a_half = lane >> 4;
    int b_t = lane >> 3, b_row = lane & 7;
    for(int kt=0;kt<16;kt++){
        cp_wait<BST-1>();
        __syncthreads();
        int cs = kt%BST;
        uint32_t atb = at_base + cs*(64*72*2);
        uint32_t xsb = xs_base + cs*(64*40*2);
        #pragma unroll
        for(int kk=0;kk<4;kk++){
            uint32_t a0,a1,a2,a3;
            ldsm_x4(a0,a1,a2,a3, atb + ((wr + a_row)*72 + kk*16 + a_half*8)*2);
            uint32_t b0,b1,b2,b3;
            ldsm_x4_t(b0,b1,b2,b3, xsb + ((kk*16 + b_row + (b_t&1)*8)*40 + wc + (b_t>>1)*8)*2);
            mma16816(c[0], a0,a1,a2,a3, b0,b1);
            mma16816(c[1], a0,a1,a2,a3, b2,b3);
        }
        __syncthreads();
        if(kt+BST<16){
            int s = (kt+BST)%BST;
            size_t ko = (size_t)(kt+BST)*64;
            cp_async16(at_base + (s*64*72 + tr0*72 + tq0*8)*2, &Ab[(size_t)(rowbase+tr0)*NN + ko + tq0*8]);
            cp_async16(at_base + (s*64*72 + tr1*72 + tq1*8)*2, &Ab[(size_t)(rowbase+tr1)*NN + ko + tq1*8]);
            cp_async16(xs_base + (s*64*40 + xr*40 + xq*8)*2,   &Xb[(ko+xr)*32 + xq*8]);
            cp_commit();
        }
    }
    float iv = 1.0f/(g_vol[b] + (float)NN*EPSF);
    float* Ob = O + (size_t)b*NN*32;
    int row0 = rowbase + wr + (lane>>2);
    int col0 = wc + (lane&3)*2;
    #pragma unroll
    for(int t=0;t<2;t++){
        *(float2*)&Ob[(size_t)row0*32 + t*8 + col0]     = make_float2(c[t][0]*iv, c[t][1]*iv);
        *(float2*)&Ob[(size_t)(row0+8)*32 + t*8 + col0] = make_float2(c[t][2]*iv, c[t][3]*iv);
    }
}

__global__ __launch_bounds__(256) void bmm_P_kernel(){ bmm_mma(g_s2eh, g_P); }

// x2 = (iv*Y@Wrel + brel) + x1@Wroot ; s2 = softmax(x2@Wp2+bp2); qs2; s2eh
__global__ __launch_bounds__(256) void k4_kernel(
        const float* __restrict__ Wrel, const float* __restrict__ brel,
        const float* __restrict__ Wroot, const float* __restrict__ Wp2,
        const float* __restrict__ bp2){
    __shared__ float Wr[32][33], Wo[32][33], Wp[32][17];
    __shared__ float brs[32], bps[16];
    __shared__ float Ys[64][33], Xs[64][33], x2s[64][33], lgS[64][17];
    int tid = threadIdx.x;
    int rowbase = blockIdx.x*64;
    int b = rowbase >> 10;
    float iv = 1.0f/(g_vol[b] + (float)NN*EPSF);
    for(int i=tid;i<1024;i+=256){ int k=i>>5,c=i&31; Wr[k][c]=Wrel[i]; Wo[k][c]=Wroot[i]; }
    for(int i=tid;i<512;i+=256){ int k=i>>4,c=i&15; Wp[k][c]=Wp2[i]; }
    if(tid<32) brs[tid]=brel[tid];
    if(tid<16) bps[tid]=bp2[tid];
    for(int i=tid;i<2048;i+=256){ int r=i>>5,c=i&31;
        Ys[r][c]=g_Y[(rowbase+r)*32+c]*iv; Xs[r][c]=g_x1[(rowbase+r)*32+c]; }
    __syncthreads();
    {
        int col = tid & 31, rg = tid >> 5;
        float a8[8];
        #pragma unroll
        for(int rr=0;rr<8;rr++) a8[rr] = brs[col];
        #pragma unroll
        for(int k=0;k<32;k++){
            float wrv = Wr[k][col], wo = Wo[k][col];
            #pragma unroll
            for(int rr=0;rr<8;rr++){
                int row = rg*8+rr;
                a8[rr] += Ys[row][k]*wrv + Xs[row][k]*wo;
            }
        }
        #pragma unroll
        for(int rr=0;rr<8;rr++){
            int row = rg*8+rr;
            x2s[row][col] = a8[rr];
            g_x2[(rowbase+row)*32+col] = a8[rr];
        }
    }
    __syncthreads();
    {
        int row = tid>>2, cq = tid&3;
        float lg[4];
        #pragma unroll
        for(int c=0;c<4;c++) lg[c]=bps[cq*4+c];
        #pragma unroll
        for(int k=0;k<32;k++){
            float xv = x2s[row][k];
            #pragma unroll
            for(int c=0;c<4;c++) lg[c] += xv*Wp[k][cq*4+c];
        }
        #pragma unroll
        for(int c=0;c<4;c++) lgS[row][cq*4+c]=lg[c];
    }
    __syncthreads();
    if(tid<64){
        int row = tid, grow = rowbase + row;
        float m = lgS[row][0];
        #pragma unroll
        for(int j=1;j<16;j++) m = fmaxf(m, lgS[row][j]);
        float e[16], sum=0.f;
        #pragma unroll
        for(int j=0;j<16;j++){ e[j]=expf(lgS[row][j]-m); sum+=e[j]; }
        float inv = 1.0f/sum, q=0.f;
        #pragma unroll
        for(int j=0;j<16;j++){
            float pv = e[j]*inv;
            g_s2[grow*16+j]=pv;
            g_s2eh[grow*32+j]=__float2half(pv);
            q += pv*pv;
        }
        g_s2eh[grow*32+16]=__float2half(1.0f);
        #pragma unroll
        for(int j=17;j<32;j++) g_s2eh[grow*32+j]=__float2half(0.0f);
        g_qs2[grow]=q;
    }
}

// red += s2^T [P(0:16)|s2|x2] over 64-row slices ; den2 partial folded in
__global__ void k6a_kernel(){
    int b = blockIdx.y, tid = threadIdx.x;      // 256
    int rb = blockIdx.x*64;
    int k = tid >> 4, cg = tid & 15;
    __shared__ float Mc[32][68];
    float acc[4] = {0,0,0,0};
    float dp = 0.f;
    for(int ch=0;ch<2;ch++){
        int base = b*NN + rb + ch*32;
        __syncthreads();
        for(int i=tid;i<32*64;i+=256){
            int r=i>>6, c=i&63;
            int row = base + r;
            float v;
            if(c<16) v = g_P[row*32 + c];
            else if(c<32) v = g_s2[row*16 + (c-16)];
            else v = g_x2[row*32 + (c-32)];
            Mc[r][c] = v;
        }
        __syncthreads();
        if(tid<32) dp += (g_P[(base+tid)*32+16] + EPSF)*g_qs2[base+tid];
        #pragma unroll 4
        for(int r=0;r<32;r++){
            float s2v = Mc[r][16+k];
            float4 m = *(const float4*)&Mc[r][cg*4];
            acc[0] += s2v*m.x; acc[1] += s2v*m.y; acc[2] += s2v*m.z; acc[3] += s2v*m.w;
        }
    }
    #pragma unroll
    for(int j=0;j<4;j++)
        atomicAdd(&g_red[b*1024 + k*64 + cg*4 + j], acc[j]);
    dp = blockReduceSum(dp);
    if(tid==0) atomicAdd(&g_den2[b], dp);
}

// per-batch tail: tdd, ortho1, ortho2, mincut-normalize + conv2 + MLP + log_softmax
__global__ void tail_kernel(const float* __restrict__ Wrel2, const float* __restrict__ brel2,
                            const float* __restrict__ Wroot2,
                            const float* __restrict__ W2, const float* __restrict__ b2,
                            const float* __restrict__ W3, const float* __restrict__ b3,
                            float* __restrict__ out){
    int tid = threadIdx.x;                       // 256
    int b = blockIdx.x;
    float td = 0.f;
    for(int n=tid;n<NN;n+=256) td += g_dflat[b*NN+n]*g_qn[b*NN+n];
    td = blockReduceSum(td);
    if(tid==0) g_tdd[b] = td;
    {
        const float* ssb = g_ss + b*KC*KC;
        float p = 0.f;
        for(int i=tid;i<KC*KC;i+=256){ float x=ssb[i]; p += x*x; }
        float ssn = sqrtf(blockReduceSum(p));
        float inv = 1.0f/ssn;
        p = 0.f;
        for(int i=tid;i<KC*KC;i+=256){
            float d = ssb[i]*inv - ((i%(KC+1))==0 ? 1.0f : 0.0f);
            p += d*d;
        }
        p = blockReduceSum(p);
        if(tid==0) g_o1b[b] = p;
    }
    {
        float x = g_red[b*1024 + (tid>>4)*64 + 16 + (tid&15)];
        float ssn2 = sqrtf(blockReduceSum(x*x));
        float d = x/ssn2 - ((tid%17)==0 ? 0.25f : 0.0f);
        float fb = blockReduceSum(d*d);
        if(tid==0) g_o2b[b] = sqrtf(fb);
    }
    __shared__ float oa[16][17];
    __shared__ float dk[16], ca[16], mS[32], oS[32], xsum[32], hsh[32], lsh[16];
    { int k=tid>>4, l=tid&15; float x=g_red[b*1024 + k*64 + l]; if(k==l) x=0.f; oa[k][l]=x; }
    __syncthreads();
    if(tid<16){
        float rs=0.f; for(int l=0;l<16;l++) rs += oa[tid][l];
        dk[tid] = sqrtf(rs + EPSF) + EPSF;
    }
    __syncthreads();
    { int k=tid>>4, l=tid&15; oa[k][l] = oa[k][l]/(dk[k]*dk[l]); }
    __syncthreads();
    if(tid<16){ float c=0.f; for(int k=0;k<16;k++) c += oa[k][tid]; ca[tid]=c; }
    __syncthreads();
    if(tid<32){
        float m=0.f, o=0.f;
        for(int l=0;l<16;l++){ float ox=g_red[b*1024 + l*64 + 32 + tid]; m += ca[l]*ox; o += ox; }
        mS[tid]=m; oS[tid]=o;
    }
    __syncthreads();
    if(tid<32){
        float x = 16.0f*brel2[tid];
        for(int g=0;g<32;g++) x += mS[g]*Wrel2[g*32+tid] + oS[g]*Wroot2[g*32+tid];
        xsum[tid] = x;
    }
    __syncthreads();
    if(tid<32){
        float h = b2[tid];
        for(int g=0;g<32;g++) h += xsum[g]*W2[g*32+tid];
        hsh[tid] = fmaxf(h, 0.f);
    }
    __syncthreads();
    if(tid<10){
        float lg = b3[tid];
        for(int g=0;g<32;g++) lg += hsh[g]*W3[g*10+tid];
        lsh[tid] = lg;
    }
    __syncthreads();
    if(tid==0){
        float m = lsh[0];
        for(int o=1;o<10;o++) m = fmaxf(m, lsh[o]);
        float s = 0.f;
        for(int o=0;o<10;o++) s += expf(lsh[o]-m);
        float lse = m + logf(s);
        for(int o=0;o<10;o++) out[b*10+o] = lsh[o]-lse;
    }
}

__global__ void loss_kernel(float* __restrict__ out){
    int tid = threadIdx.x;                       // 256
    float v = 0.f;
    if(tid<BB){
        float tddf = g_tdd[tid];
        v = (tddf - g_tda[tid])/(tddf + EPSF);
    }
    float ct_loss = blockReduceSum(v)*(1.0f/BB);
    v = (tid<BB) ? g_o1b[tid] : 0.f;
    float ortho1 = sqrtf(blockReduceSum(v));
    v = 0.f;
    if(tid<BB){
        float num = 0.f;
        for(int k=0;k<K2C;k++) num += g_red[tid*1024 + k*64 + k];
        v = -num/g_den2[tid];
    }
    float mc_loss = blockReduceSum(v)*(1.0f/BB);
    v = (tid<BB) ? g_o2b[tid] : 0.f;
    float ortho2 = blockReduceSum(v)*(1.0f/BB);
    if(tid==0){ out[160] = ct_loss + ortho1; out[161] = mc_loss + ortho2; }
}

// ---------------- launch ----------------
extern "C" void kernel_launch(void* const* d_in, const int* in_sizes, int n_in,
                              void* d_out, int out_size){
    const float* x       = (const float*)d_in[0];
    const float* adj     = (const float*)d_in[1];
    const float* W_lin1  = (const float*)d_in[3];
    const float* b_lin1  = (const float*)d_in[4];
    const float* W_pool1 = (const float*)d_in[5];
    const float* b_pool1 = (const float*)d_in[6];
    const float* W_pool2 = (const float*)d_in[7];
    const float* b_pool2 = (const float*)d_in[8];
    const float* Wrel1   = (const float*)d_in[9];
    const float* brel1   = (const float*)d_in[10];
    const float* Wroot1  = (const float*)d_in[11];
    const float* Wrel2   = (const float*)d_in[12];
    const float* brel2   = (const float*)d_in[13];
    const float* Wroot2  = (const float*)d_in[14];
    const float* W_lin2  = (const float*)d_in[15];
    const float* b_lin2  = (const float*)d_in[16];
    const float* W_lin3  = (const float*)d_in[17];
    const float* b_lin3  = (const float*)d_in[18];
    float* out = (float*)d_out;

    zero_kernel<<<64,256>>>();
    lin1pool_kernel<<<BB*NN/64, 128>>>(x, W_lin1, b_lin1, W_pool1, b_pool1);
    ct_main_kernel<<<dim3(8,8,BB), 256>>>(adj);
    k4_kernel<<<BB*NN/64, 256>>>(Wrel1, brel1, Wroot1, W_pool2, b_pool2);
    bmm_P_kernel<<<dim3(16,BB), 256>>>();
    k6a_kernel<<<dim3(16,BB), 256>>>();
    tail_kernel<<<BB, 256>>>(Wrel2, brel2, Wroot2, W_lin2, b_lin2, W_lin3, b_lin3, out);
    loss_kernel<<<1, 256>>>(out);
}